// round 16
// baseline (speedup 1.0000x reference)
#include <cuda_runtime.h>
#include <cuda_fp16.h>
#include <stdint.h>

#define BATCH 16
#define SEQ   2048
#define HID   1024
#define VOCAB 250002
#define SM1   2047                 // S-1
#define MROWS (BATCH * SM1)        // 32752 colbert rows
#define MPAD  32768                // padded to multiple of 128
#define EPSV  1e-12f

static const size_t OFF_SPARSE  = (size_t)BATCH * HID;                 // 16384
static const size_t OFF_COLBERT = OFF_SPARSE + (size_t)BATCH * VOCAB;  // 4016416

// ---------------- device scratch (static, no allocs) -----------------------
__device__ float g_ssq_part[(size_t)MROWS * 4];
__device__ int   g_is64;
__device__ __half g_Wh[(size_t)HID * HID];   // Wt[n][k] = fp16(W[k][n])
__device__ __half g_Af[(size_t)MPAD * HID];  // A rows (skipping CLS), fp16
__device__ __half g_C[(size_t)MPAD * HID];   // unnormalized colbert C, fp16
// rows MROWS..MPAD-1 of g_Af are never written -> stay zero (module init)

// ---------------- PTX helpers (plain sm_103-safe: sm_80 era) ----------------
__device__ __forceinline__ uint32_t smem_u32(const void* p) {
    uint32_t a;
    asm("{ .reg .u64 t; cvta.to.shared.u64 t, %1; cvt.u32.u64 %0, t; }" : "=r"(a) : "l"(p));
    return a;
}
#define CP16(dst, src) \
    asm volatile("cp.async.cg.shared.global [%0], [%1], 16;" :: "r"(dst), "l"(src))
#define CPCOMMIT() asm volatile("cp.async.commit_group;" ::: "memory")
#define CPWAIT1()  asm volatile("cp.async.wait_group 1;" ::: "memory")
#define CPWAIT0()  asm volatile("cp.async.wait_group 0;" ::: "memory")

#define LDMX4(r, addr)                                                  \
    asm volatile("ldmatrix.sync.aligned.m8n8.x4.shared.b16 {%0,%1,%2,%3}, [%4];" \
        : "=r"((r)[0]), "=r"((r)[1]), "=r"((r)[2]), "=r"((r)[3]) : "r"(addr))

#define MMA_F16(d, a, b0, b1)                                           \
    asm volatile("mma.sync.aligned.m16n8k16.row.col.f32.f16.f16.f32 "   \
        "{%0,%1,%2,%3}, {%4,%5,%6,%7}, {%8,%9}, {%0,%1,%2,%3};"         \
        : "+f"((d)[0]), "+f"((d)[1]), "+f"((d)[2]), "+f"((d)[3])        \
        : "r"((a)[0]), "r"((a)[1]), "r"((a)[2]), "r"((a)[3]), "r"(b0), "r"(b1))

// ---------------- GEMM geometry --------------------------------------------
// 64B rows with XOR swizzle: byte = row*64 + ((chunk ^ ((row>>1)&3)) << 4)
// CTA tile 128(M) x 256(N); ring stage = PAIR of two BK=32 chunks.
// Pair layout: [A0 8KB | B0 16KB | A1 8KB | B1 16KB] = 48KB.
#define BM 128
#define BN 256
#define BK 32
#define NPAIR  3
#define ATILEB (128 * 64)             // 8192
#define BTILEB (256 * 64)             // 16384
#define CHUNKB (ATILEB + BTILEB)      // 24576
#define PAIRB  (2 * CHUNKB)           // 49152
#define SMEMB  (NPAIR * PAIRB)        // 147456 -> 1 CTA/SM

// ---------------------------------------------------------------------------
__global__ void detect_i64_kernel(const unsigned int* __restrict__ w) {
    __shared__ int anynz;
    if (threadIdx.x == 0) anynz = 0;
    __syncthreads();
    int loc = 0;
    for (int i = threadIdx.x; i < BATCH * SEQ / 2; i += blockDim.x)
        loc |= (w[2 * i + 1] != 0u);
    if (loc) atomicOr(&anynz, 1);
    __syncthreads();
    if (threadIdx.x == 0) g_is64 = (anynz == 0);
}

// ---------------------------------------------------------------------------
__global__ void dense_kernel(const float* __restrict__ hs, float* __restrict__ out) {
    int b = blockIdx.x, t = threadIdx.x;
    const float4* x4 = (const float4*)(hs + (size_t)b * SEQ * HID);
    float4 v = x4[t];
    float s = v.x * v.x + v.y * v.y + v.z * v.z + v.w * v.w;
    #pragma unroll
    for (int o = 16; o; o >>= 1) s += __shfl_xor_sync(0xffffffffu, s, o);
    __shared__ float red[8];
    __shared__ float scv;
    if ((t & 31) == 0) red[t >> 5] = s;
    __syncthreads();
    if (t == 0) {
        float a = 0.f;
        #pragma unroll
        for (int i = 0; i < 8; i++) a += red[i];
        scv = 1.f / fmaxf(sqrtf(a), EPSV);
    }
    __syncthreads();
    float sc = scv;
    v.x *= sc; v.y *= sc; v.z *= sc; v.w *= sc;
    ((float4*)(out + (size_t)b * HID))[t] = v;
}

// ---------------------------------------------------------------------------
// Fused: A fp16 convert (with CLS-skip remap) + sparse relu-dot scatter-max.
// ---------------------------------------------------------------------------
__global__ void fused_prep_kernel(const float* __restrict__ hs,
                                  const float* __restrict__ sW,
                                  const float* __restrict__ sb,
                                  const void* __restrict__ ids,
                                  float* __restrict__ sparse_out) {
    __shared__ float4 w4[HID / 4];
    const int tid = threadIdx.x;
    for (int i = tid; i < HID / 4; i += 256)
        w4[i] = ((const float4*)sW)[i];

    const int base = blockIdx.x * 8;           // first hs row of this block

    // phase A: convert 8 rows to fp16 into g_Af (skip token-0 rows)
    #pragma unroll
    for (int i = 0; i < 8; i++) {
        const int r = base + i;
        if ((r & (SEQ - 1)) != 0) {
            const int m = r - 1 - (r >> 11);   // inverse remap (SEQ = 2^11)
            float4 v = *(const float4*)(hs + (size_t)r * HID + tid * 4);
            __half2 h0 = __floats2half2_rn(v.x, v.y);
            __half2 h1 = __floats2half2_rn(v.z, v.w);
            ((uint2*)g_Af)[(size_t)m * (HID / 4) + tid] =
                make_uint2(*(uint32_t*)&h0, *(uint32_t*)&h1);
        }
    }
    __syncthreads();                           // w4 ready (also phase spacing)

    // phase B: warp w computes sparse weight of row base+w
    const int w = tid >> 5, lane = tid & 31;
    const int r = base + w;
    const float4* x4 = (const float4*)(hs + (size_t)r * HID);
    float s = 0.f;
    #pragma unroll
    for (int i = 0; i < 8; i++) {
        float4 a = x4[lane + i * 32];
        float4 b = w4[lane + i * 32];
        s += a.x * b.x + a.y * b.y + a.z * b.z + a.w * b.w;
    }
    #pragma unroll
    for (int o = 16; o; o >>= 1) s += __shfl_xor_sync(0xffffffffu, s, o);
    if (lane == 0) {
        float tw = s + sb[0];
        if (tw > 0.f) {
            long long id = g_is64 ? ((const long long*)ids)[r]
                                  : (long long)((const int*)ids)[r];
            if (id >= 4) {
                int b = r >> 11;               // batch = r / SEQ
                atomicMax((unsigned int*)(sparse_out + (size_t)b * VOCAB + (size_t)id),
                          __float_as_uint(tw));
            }
        }
    }
}

// ---------------------------------------------------------------------------
// W transpose + fp16 convert: Wt[n][k] = fp16(W[k][n])
// ---------------------------------------------------------------------------
__global__ void wt_split_kernel(const float* __restrict__ W) {
    __shared__ float tile[32][33];
    int n0 = blockIdx.x * 32, k0 = blockIdx.y * 32;
    int tx = threadIdx.x & 31, ty = threadIdx.x >> 5;   // 32 x 8
    #pragma unroll
    for (int i = ty; i < 32; i += 8)
        tile[i][tx] = W[(size_t)(k0 + i) * HID + n0 + tx];
    __syncthreads();
    #pragma unroll
    for (int i = ty; i < 32; i += 8)
        g_Wh[(size_t)(n0 + i) * HID + k0 + tx] = __float2half_rn(tile[tx][i]);
}

// ---------------------------------------------------------------------------
// colbert GEMM: plain fp16 (fp32 accum), 128x256 CTA tile, warp tile 64x64,
// K=64 per ring stage (two BK=32 chunks), 3-pair cp.async ring, one
// __syncthreads per pair, swizzled 64B rows, 1 CTA/SM.
// ---------------------------------------------------------------------------
__global__ __launch_bounds__(256, 1)
void colbert_mma_kernel(const float* __restrict__ bias,
                        const float* __restrict__ amask)
{
    extern __shared__ char sm[];
    const uint32_t smb = smem_u32(sm);
    const int tid = threadIdx.x, wid = tid >> 5, lane = tid & 31;
    const int bx = blockIdx.x;                 // N tile (0..3)
    const int m0 = blockIdx.y * BM;
    const int n0 = bx * BN;
    const int wm = wid & 1, wn = wid >> 1;     // warp grid 2(M) x 4(N), 64x64

    const __half* Af = g_Af + (size_t)m0 * HID;
    const __half* Bh = g_Wh + (size_t)n0 * HID;

    // cp.async mapping per chunk:
    //   A: 512 16B-chunks -> 2/thread (rows r0, r0+64)
    //   B: 1024 16B-chunks -> 4/thread (rows r0, +64, +128, +192)
    // swizzle x = (row>>1)&3 invariant under row+=64.
    const int r0 = tid >> 2, c0 = tid & 3;
    const uint32_t x0  = ((uint32_t)r0 >> 1) & 3;
    const uint32_t db  = (uint32_t)(r0 * 64) + (((uint32_t)c0 ^ x0) << 4);
    const size_t  ob   = (size_t)r0 * HID + c0 * 8;

    // ldmatrix lane constants
    const int lr = lane & 15, lc = lane >> 4;
    const uint32_t lx = ((uint32_t)lr >> 1) & 3;
    const uint32_t lrow = (uint32_t)lr * 64;
    const uint32_t cb0 = (((uint32_t)lc ^ lx) << 4);
    const uint32_t cb1 = (((uint32_t)(2 + lc) ^ lx) << 4);

    float acc[4][8][4];                        // [mi][n8 j][frag] = 128 regs
    #pragma unroll
    for (int a = 0; a < 4; a++)
        #pragma unroll
        for (int b = 0; b < 8; b++)
            #pragma unroll
            for (int c = 0; c < 4; c++) acc[a][b][c] = 0.f;

    // preload pairs 0,1 (one commit per pair)
    #pragma unroll
    for (int p = 0; p < NPAIR - 1; p++) {
        #pragma unroll
        for (int ksub = 0; ksub < 2; ksub++) {
            const uint32_t sa = smb + p * PAIRB + ksub * CHUNKB;
            const uint32_t sbB = sa + ATILEB;
            const int k0 = p * 64 + ksub * BK;
            CP16(sa + db,           Af + ob + k0);
            CP16(sa + db + 64 * 64, Af + ob + (size_t)64 * HID + k0);
            #pragma unroll
            for (int q = 0; q < 4; q++)
                CP16(sbB + db + q * 64 * 64,
                     Bh + ob + (size_t)(q * 64) * HID + k0);
        }
        CPCOMMIT();
    }

    const int NITER = HID / 64;    // 16 pair-iterations
    int sidx = 0, widx = NPAIR - 1;
    for (int ci = 0; ci < NITER; ci++) {
        if (ci < NITER - 1) CPWAIT1(); else CPWAIT0();
        __syncthreads();

        if (ci + 2 < NITER) {      // issue pair ci+2
            #pragma unroll
            for (int ksub = 0; ksub < 2; ksub++) {
                const uint32_t sa = smb + widx * PAIRB + ksub * CHUNKB;
                const uint32_t sbB = sa + ATILEB;
                const int k0 = (ci + 2) * 64 + ksub * BK;
                CP16(sa + db,           Af + ob + k0);
                CP16(sa + db + 64 * 64, Af + ob + (size_t)64 * HID + k0);
                #pragma unroll
                for (int q = 0; q < 4; q++)
                    CP16(sbB + db + q * 64 * 64,
                         Bh + ob + (size_t)(q * 64) * HID + k0);
            }
            CPCOMMIT();
        }

        #pragma unroll
        for (int ksub = 0; ksub < 2; ksub++) {
            const uint32_t sa  = smb + sidx * PAIRB + ksub * CHUNKB;
            const uint32_t sbB = sa + ATILEB;
            #pragma unroll
            for (int ks = 0; ks < 2; ks++) {
                const uint32_t cbk = ks ? cb1 : cb0;
                uint32_t bh[4][4];
                #pragma unroll
                for (int ni = 0; ni < 4; ni++) {
                    uint32_t rb = sbB + (uint32_t)((wn * 64 + ni * 16) * 64)
                                + lrow + cbk;
                    LDMX4(bh[ni], rb);
                }
                #pragma unroll
                for (int mi = 0; mi < 4; mi++) {
                    uint32_t ah[4];
                    uint32_t ra = sa + (uint32_t)((wm * 64 + mi * 16) * 64)
                                + lrow + cbk;
                    LDMX4(ah, ra);
                    #pragma unroll
                    for (int ni = 0; ni < 4; ni++)
                        #pragma unroll
                        for (int sub = 0; sub < 2; sub++)
                            MMA_F16(acc[mi][ni * 2 + sub], ah,
                                    bh[ni][sub], bh[ni][sub + 2]);
                }
            }
        }
        sidx = (sidx == NPAIR - 1) ? 0 : sidx + 1;
        widx = (widx == NPAIR - 1) ? 0 : widx + 1;
    }

    // -------- epilogue: bias + mask, fp16 C store, ssq partials -------------
    float bj[8][2];
    #pragma unroll
    for (int j = 0; j < 8; j++) {
        int cb = n0 + wn * 64 + j * 8 + (lane & 3) * 2;
        bj[j][0] = bias[cb];
        bj[j][1] = bias[cb + 1];
    }

    float* ssq_sm = (float*)sm;    // [128][4]; pipeline done, smem reusable

    __syncthreads();
    #pragma unroll
    for (int mi = 0; mi < 4; mi++)
        #pragma unroll
        for (int h = 0; h < 2; h++) {
            const int rt = wm * 64 + mi * 16 + h * 8 + (lane >> 2);
            const int m  = m0 + rt;
            const bool mv = m < MROWS;
            const float mk = mv ? amask[m + m / SM1 + 1] : 0.f;
            float s = 0.f;
            #pragma unroll
            for (int j = 0; j < 8; j++) {
                float v0 = (acc[mi][j][h * 2 + 0] + bj[j][0]) * mk;
                float v1 = (acc[mi][j][h * 2 + 1] + bj[j][1]) * mk;
                s += v0 * v0 + v1 * v1;
                if (mv) {
                    int cb = n0 + wn * 64 + j * 8 + (lane & 3) * 2;
                    *(__half2*)(g_C + (size_t)m * HID + cb) =
                        __floats2half2_rn(v0, v1);
                }
            }
            s += __shfl_xor_sync(0xffffffffu, s, 1);
            s += __shfl_xor_sync(0xffffffffu, s, 2);
            if ((lane & 3) == 0) ssq_sm[rt * 4 + wn] = s;
        }
    __syncthreads();
    if (tid < 128) {
        int m = m0 + tid;
        if (m < MROWS) {
            float s = ssq_sm[tid * 4 + 0] + ssq_sm[tid * 4 + 1]
                    + ssq_sm[tid * 4 + 2] + ssq_sm[tid * 4 + 3];
            g_ssq_part[(size_t)m * 4 + bx] = s;
        }
    }
}

// ---------------------------------------------------------------------------
// normalize colbert rows: block = 2 rows. 2 threads compute scales (fixed-
// order 4-partial sum -> deterministic), then 128 threads/row rescale fp16 C
// into fp32 output.
// ---------------------------------------------------------------------------
__global__ void colbert_norm_kernel(float* __restrict__ Cout) {
    __shared__ float ssc[2];
    const int tid = threadIdx.x;
    const int base = blockIdx.x * 2;
    if (tid < 2) {
        const float* p = g_ssq_part + (size_t)(base + tid) * 4;
        float ss = 0.f;
        #pragma unroll
        for (int n = 0; n < 4; n++) ss += p[n];
        ssc[tid] = 1.f / fmaxf(sqrtf(ss), EPSV);
    }
    __syncthreads();
    const int row = base + (tid >> 7);
    const float sc = ssc[tid >> 7];
    const int col = (tid & 127) * 8;           // 8 halfs per thread
    const uint4 hv = *(const uint4*)(g_C + (size_t)row * HID + col);
    float2 f0 = __half22float2(*(const __half2*)&hv.x);
    float2 f1 = __half22float2(*(const __half2*)&hv.y);
    float2 f2 = __half22float2(*(const __half2*)&hv.z);
    float2 f3 = __half22float2(*(const __half2*)&hv.w);
    float* dst = Cout + (size_t)row * HID + col;
    *(float4*)dst       = make_float4(f0.x * sc, f0.y * sc, f1.x * sc, f1.y * sc);
    *(float4*)(dst + 4) = make_float4(f2.x * sc, f2.y * sc, f3.x * sc, f3.y * sc);
}

// ---------------------------------------------------------------------------
extern "C" void kernel_launch(void* const* d_in, const int* in_sizes, int n_in,
                              void* d_out, int out_size) {
    const float* hs  = (const float*)d_in[0];
    const float* am  = (const float*)d_in[1];
    const void*  ids = d_in[2];
    const float* sW  = (const float*)d_in[3];
    const float* sb  = (const float*)d_in[4];
    const float* cW  = (const float*)d_in[5];
    const float* cb  = (const float*)d_in[6];

    float* out     = (float*)d_out;
    float* dense   = out;
    float* sparse  = out + OFF_SPARSE;
    float* colbert = out + OFF_COLBERT;

    // one-time resources (created on the uncaptured correctness call)
    static cudaStream_t s_side = nullptr;
    static cudaEvent_t  e_fork = nullptr, e_join = nullptr;
    if (!s_side) {
        cudaStreamCreateWithFlags(&s_side, cudaStreamNonBlocking);
        cudaEventCreateWithFlags(&e_fork, cudaEventDisableTiming);
        cudaEventCreateWithFlags(&e_join, cudaEventDisableTiming);
        cudaFuncSetAttribute(colbert_mma_kernel,
                             cudaFuncAttributeMaxDynamicSharedMemorySize, SMEMB);
    }

    // fork: side stream runs the GEMM-independent small kernels
    cudaEventRecord(e_fork, 0);
    cudaStreamWaitEvent(s_side, e_fork, 0);
    wt_split_kernel<<<dim3(32, 32), 256, 0, s_side>>>(cW);
    dense_kernel<<<BATCH, 256, 0, s_side>>>(hs, dense);
    cudaEventRecord(e_join, s_side);

    // main chain: memset -> detect -> fused_prep
    cudaMemsetAsync(sparse, 0, (size_t)BATCH * VOCAB * sizeof(float), 0);
    detect_i64_kernel<<<1, 256>>>((const unsigned int*)ids);
    fused_prep_kernel<<<4096, 256>>>(hs, sW, sb, ids, sparse);

    // join before GEMM (needs g_Wh from wt_split)
    cudaStreamWaitEvent(0, e_join, 0);
    colbert_mma_kernel<<<dim3(4, 256), 256, SMEMB>>>(cb, am);
    colbert_norm_kernel<<<MROWS / 2, 256>>>(colbert);
}

// round 17
// speedup vs baseline: 1.0599x; 1.0599x over previous
#include <cuda_runtime.h>
#include <cuda_fp16.h>
#include <stdint.h>

#define BATCH 16
#define SEQ   2048
#define HID   1024
#define VOCAB 250002
#define SM1   2047                 // S-1
#define MROWS (BATCH * SM1)        // 32752 colbert rows
#define MPAD  32768                // padded to multiple of 128
#define EPSV  1e-12f

// GEMM M-split for norm overlap: y-tiles [0,128) -> rows [0,16384)
#define YHALF 128
#define NORMBLK_H0 (16384 / 2)            // norm blocks for rows < 16384
#define NORMBLK_H1 ((MROWS - 16384 + 1) / 2)

static const size_t OFF_SPARSE  = (size_t)BATCH * HID;                 // 16384
static const size_t OFF_COLBERT = OFF_SPARSE + (size_t)BATCH * VOCAB;  // 4016416

// ---------------- device scratch (static, no allocs) -----------------------
__device__ float g_ssq_part[(size_t)MROWS * 8];
__device__ int   g_is64;
__device__ __half g_Wh[(size_t)HID * HID];   // Wt[n][k] = fp16(W[k][n])
__device__ __half g_Af[(size_t)MPAD * HID];  // A rows (skipping CLS), fp16
__device__ __half g_C[(size_t)MPAD * HID];   // unnormalized colbert C, fp16
// rows MROWS..MPAD-1 of g_Af are never written -> stay zero (module init)

// ---------------- PTX helpers (plain sm_103-safe: sm_80 era) ----------------
__device__ __forceinline__ uint32_t smem_u32(const void* p) {
    uint32_t a;
    asm("{ .reg .u64 t; cvta.to.shared.u64 t, %1; cvt.u32.u64 %0, t; }" : "=r"(a) : "l"(p));
    return a;
}
#define CP16(dst, src) \
    asm volatile("cp.async.cg.shared.global [%0], [%1], 16;" :: "r"(dst), "l"(src))
#define CPCOMMIT() asm volatile("cp.async.commit_group;" ::: "memory")
#define CPWAIT1()  asm volatile("cp.async.wait_group 1;" ::: "memory")
#define CPWAIT0()  asm volatile("cp.async.wait_group 0;" ::: "memory")

#define LDMX4(r, addr)                                                  \
    asm volatile("ldmatrix.sync.aligned.m8n8.x4.shared.b16 {%0,%1,%2,%3}, [%4];" \
        : "=r"((r)[0]), "=r"((r)[1]), "=r"((r)[2]), "=r"((r)[3]) : "r"(addr))

#define MMA_F16(d, a, b0, b1)                                           \
    asm volatile("mma.sync.aligned.m16n8k16.row.col.f32.f16.f16.f32 "   \
        "{%0,%1,%2,%3}, {%4,%5,%6,%7}, {%8,%9}, {%0,%1,%2,%3};"         \
        : "+f"((d)[0]), "+f"((d)[1]), "+f"((d)[2]), "+f"((d)[3])        \
        : "r"((a)[0]), "r"((a)[1]), "r"((a)[2]), "r"((a)[3]), "r"(b0), "r"(b1))

// ---------------- GEMM geometry (R14-proven config) -------------------------
// 64B rows with XOR swizzle: byte = row*64 + ((chunk ^ ((row>>1)&3)) << 4)
// Ring stage = PAIR of two BK=32 chunks (A0,B0,A1,B1), one commit per pair.
#define BM 128
#define BN 128
#define BK 32
#define NPAIR  3
#define TILEB  (128 * 64)             // 8192 bytes per operand chunk-tile
#define PAIRB  (4 * TILEB)            // 32768
#define SMEMB  (NPAIR * PAIRB)        // 98304 -> 2 CTAs/SM

// ---------------------------------------------------------------------------
__global__ void detect_i64_kernel(const unsigned int* __restrict__ w) {
    __shared__ int anynz;
    if (threadIdx.x == 0) anynz = 0;
    __syncthreads();
    int loc = 0;
    for (int i = threadIdx.x; i < BATCH * SEQ / 2; i += blockDim.x)
        loc |= (w[2 * i + 1] != 0u);
    if (loc) atomicOr(&anynz, 1);
    __syncthreads();
    if (threadIdx.x == 0) g_is64 = (anynz == 0);
}

// ---------------------------------------------------------------------------
__global__ void dense_kernel(const float* __restrict__ hs, float* __restrict__ out) {
    int b = blockIdx.x, t = threadIdx.x;
    const float4* x4 = (const float4*)(hs + (size_t)b * SEQ * HID);
    float4 v = x4[t];
    float s = v.x * v.x + v.y * v.y + v.z * v.z + v.w * v.w;
    #pragma unroll
    for (int o = 16; o; o >>= 1) s += __shfl_xor_sync(0xffffffffu, s, o);
    __shared__ float red[8];
    __shared__ float scv;
    if ((t & 31) == 0) red[t >> 5] = s;
    __syncthreads();
    if (t == 0) {
        float a = 0.f;
        #pragma unroll
        for (int i = 0; i < 8; i++) a += red[i];
        scv = 1.f / fmaxf(sqrtf(a), EPSV);
    }
    __syncthreads();
    float sc = scv;
    v.x *= sc; v.y *= sc; v.z *= sc; v.w *= sc;
    ((float4*)(out + (size_t)b * HID))[t] = v;
}

// ---------------------------------------------------------------------------
// Fused: A fp16 convert (with CLS-skip remap) + sparse relu-dot scatter-max.
// ---------------------------------------------------------------------------
__global__ void fused_prep_kernel(const float* __restrict__ hs,
                                  const float* __restrict__ sW,
                                  const float* __restrict__ sb,
                                  const void* __restrict__ ids,
                                  float* __restrict__ sparse_out) {
    __shared__ float4 w4[HID / 4];
    const int tid = threadIdx.x;
    for (int i = tid; i < HID / 4; i += 256)
        w4[i] = ((const float4*)sW)[i];

    const int base = blockIdx.x * 8;           // first hs row of this block

    // phase A: convert 8 rows to fp16 into g_Af (skip token-0 rows)
    #pragma unroll
    for (int i = 0; i < 8; i++) {
        const int r = base + i;
        if ((r & (SEQ - 1)) != 0) {
            const int m = r - 1 - (r >> 11);   // inverse remap (SEQ = 2^11)
            float4 v = *(const float4*)(hs + (size_t)r * HID + tid * 4);
            __half2 h0 = __floats2half2_rn(v.x, v.y);
            __half2 h1 = __floats2half2_rn(v.z, v.w);
            ((uint2*)g_Af)[(size_t)m * (HID / 4) + tid] =
                make_uint2(*(uint32_t*)&h0, *(uint32_t*)&h1);
        }
    }
    __syncthreads();                           // w4 ready (also phase spacing)

    // phase B: warp w computes sparse weight of row base+w
    const int w = tid >> 5, lane = tid & 31;
    const int r = base + w;
    const float4* x4 = (const float4*)(hs + (size_t)r * HID);
    float s = 0.f;
    #pragma unroll
    for (int i = 0; i < 8; i++) {
        float4 a = x4[lane + i * 32];
        float4 b = w4[lane + i * 32];
        s += a.x * b.x + a.y * b.y + a.z * b.z + a.w * b.w;
    }
    #pragma unroll
    for (int o = 16; o; o >>= 1) s += __shfl_xor_sync(0xffffffffu, s, o);
    if (lane == 0) {
        float tw = s + sb[0];
        if (tw > 0.f) {
            long long id = g_is64 ? ((const long long*)ids)[r]
                                  : (long long)((const int*)ids)[r];
            if (id >= 4) {
                int b = r >> 11;               // batch = r / SEQ
                atomicMax((unsigned int*)(sparse_out + (size_t)b * VOCAB + (size_t)id),
                          __float_as_uint(tw));
            }
        }
    }
}

// ---------------------------------------------------------------------------
// W transpose + fp16 convert: Wt[n][k] = fp16(W[k][n])
// ---------------------------------------------------------------------------
__global__ void wt_split_kernel(const float* __restrict__ W) {
    __shared__ float tile[32][33];
    int n0 = blockIdx.x * 32, k0 = blockIdx.y * 32;
    int tx = threadIdx.x & 31, ty = threadIdx.x >> 5;   // 32 x 8
    #pragma unroll
    for (int i = ty; i < 32; i += 8)
        tile[i][tx] = W[(size_t)(k0 + i) * HID + n0 + tx];
    __syncthreads();
    #pragma unroll
    for (int i = ty; i < 32; i += 8)
        g_Wh[(size_t)(n0 + i) * HID + k0 + tx] = __float2half_rn(tile[tx][i]);
}

// ---------------------------------------------------------------------------
// colbert GEMM: plain fp16 (fp32 accum), 128x128 tiles, K=64 per ring stage
// (two BK=32 chunks), 3-pair cp.async ring, ONE __syncthreads per 64-K,
// swizzled 64B rows, 2 CTAs/SM. y0 = M-tile offset (split launch).
// ---------------------------------------------------------------------------
__global__ __launch_bounds__(256, 2)
void colbert_mma_kernel(const float* __restrict__ bias,
                        const float* __restrict__ amask,
                        int y0)
{
    extern __shared__ char sm[];
    const uint32_t smb = smem_u32(sm);
    const int tid = threadIdx.x, wid = tid >> 5, lane = tid & 31;
    const int bx = blockIdx.x;                 // N tile (0..7)
    const int m0 = (y0 + blockIdx.y) * BM;
    const int n0 = bx * BN;
    const int wm = wid & 1, wn = wid >> 1;     // warp grid 2(M) x 4(N)

    const __half* Af = g_Af + (size_t)m0 * HID;
    const __half* Bh = g_Wh + (size_t)n0 * HID;

    // cp.async mapping per chunk: 2x 16B per thread (rows r0, r0+64)
    const int r0 = tid >> 2, c0 = tid & 3;
    const uint32_t x0  = ((uint32_t)r0 >> 1) & 3;
    const uint32_t d0b = (uint32_t)(r0 * 64) + (((uint32_t)c0 ^ x0) << 4);
    const uint32_t d1b = d0b + 64 * 64;        // row+64: (r>>1)&3 unchanged
    const size_t o0b = (size_t)r0 * HID + c0 * 8;
    const size_t o1b = o0b + (size_t)64 * HID;

    // ldmatrix lane constants
    const int lr = lane & 15, lc = lane >> 4;
    const uint32_t lx = ((uint32_t)lr >> 1) & 3;
    const uint32_t lrow = (uint32_t)lr * 64;
    const uint32_t cb0 = (((uint32_t)lc ^ lx) << 4);
    const uint32_t cb1 = (((uint32_t)(2 + lc) ^ lx) << 4);

    float acc[4][4][4];
    #pragma unroll
    for (int a = 0; a < 4; a++)
        #pragma unroll
        for (int b = 0; b < 4; b++)
            #pragma unroll
            for (int c = 0; c < 4; c++) acc[a][b][c] = 0.f;

    // preload pairs 0,1 (one commit per pair)
    #pragma unroll
    for (int p = 0; p < NPAIR - 1; p++) {
        const uint32_t pb = smb + p * PAIRB;
        #pragma unroll
        for (int ksub = 0; ksub < 2; ksub++) {
            const uint32_t sb = pb + ksub * 2 * TILEB;
            const int k0 = p * 64 + ksub * BK;
            uint32_t d0 = sb + d0b, d1 = sb + d1b;
            size_t o0 = o0b + k0, o1 = o1b + k0;
            CP16(d0, Af + o0);         CP16(d1, Af + o1);
            CP16(d0 + TILEB, Bh + o0); CP16(d1 + TILEB, Bh + o1);
        }
        CPCOMMIT();
    }

    const int NITER = HID / 64;    // 16 pair-iterations
    int sidx = 0, widx = NPAIR - 1;
    for (int ci = 0; ci < NITER; ci++) {
        if (ci < NITER - 1) CPWAIT1(); else CPWAIT0();
        __syncthreads();

        if (ci + 2 < NITER) {      // issue pair ci+2
            const uint32_t pb = smb + widx * PAIRB;
            #pragma unroll
            for (int ksub = 0; ksub < 2; ksub++) {
                const uint32_t sb = pb + ksub * 2 * TILEB;
                const int k0 = (ci + 2) * 64 + ksub * BK;
                uint32_t d0 = sb + d0b, d1 = sb + d1b;
                size_t o0 = o0b + k0, o1 = o1b + k0;
                CP16(d0, Af + o0);         CP16(d1, Af + o1);
                CP16(d0 + TILEB, Bh + o0); CP16(d1 + TILEB, Bh + o1);
            }
            CPCOMMIT();
        }

        const uint32_t pb = smb + sidx * PAIRB;
        #pragma unroll
        for (int ksub = 0; ksub < 2; ksub++) {
            const uint32_t sb = pb + ksub * 2 * TILEB;
            #pragma unroll
            for (int ks = 0; ks < 2; ks++) {
                const uint32_t cbk = ks ? cb1 : cb0;
                uint32_t bh[2][4];
                #pragma unroll
                for (int ni = 0; ni < 2; ni++) {
                    uint32_t rb = sb + TILEB
                                + (uint32_t)((wn * 32 + ni * 16) * 64) + lrow + cbk;
                    LDMX4(bh[ni], rb);
                }
                #pragma unroll
                for (int mi = 0; mi < 4; mi++) {
                    uint32_t ah[4];
                    uint32_t ra = sb + (uint32_t)((wm * 64 + mi * 16) * 64) + lrow + cbk;
                    LDMX4(ah, ra);
                    #pragma unroll
                    for (int ni = 0; ni < 2; ni++)
                        #pragma unroll
                        for (int sub = 0; sub < 2; sub++)
                            MMA_F16(acc[mi][ni * 2 + sub], ah,
                                    bh[ni][sub], bh[ni][sub + 2]);
                }
            }
        }
        sidx = (sidx == NPAIR - 1) ? 0 : sidx + 1;
        widx = (widx == NPAIR - 1) ? 0 : widx + 1;
    }

    // -------- epilogue: bias + mask, fp16 C store, ssq partials -------------
    float bj[4][2];
    #pragma unroll
    for (int j = 0; j < 4; j++) {
        int cb = n0 + wn * 32 + j * 8 + (lane & 3) * 2;
        bj[j][0] = bias[cb];
        bj[j][1] = bias[cb + 1];
    }

    float* ssq_sm = (float*)sm;    // pipeline done, smem reusable

    __syncthreads();
    #pragma unroll
    for (int mi = 0; mi < 4; mi++)
        #pragma unroll
        for (int h = 0; h < 2; h++) {
            const int rt = wm * 64 + mi * 16 + h * 8 + (lane >> 2);
            const int m  = m0 + rt;
            const bool mv = m < MROWS;
            const float mk = mv ? amask[m + m / SM1 + 1] : 0.f;
            float s = 0.f;
            #pragma unroll
            for (int j = 0; j < 4; j++) {
                float v0 = (acc[mi][j][h * 2 + 0] + bj[j][0]) * mk;
                float v1 = (acc[mi][j][h * 2 + 1] + bj[j][1]) * mk;
                s += v0 * v0 + v1 * v1;
                if (mv) {
                    int cb = n0 + wn * 32 + j * 8 + (lane & 3) * 2;
                    *(__half2*)(g_C + (size_t)m * HID + cb) =
                        __floats2half2_rn(v0, v1);
                }
            }
            s += __shfl_xor_sync(0xffffffffu, s, 1);
            s += __shfl_xor_sync(0xffffffffu, s, 2);
            if ((lane & 3) == 0) ssq_sm[rt * 4 + wn] = s;
        }
    __syncthreads();
    if (tid < 128) {
        int m = m0 + tid;
        if (m < MROWS) {
            float s = ssq_sm[tid * 4 + 0] + ssq_sm[tid * 4 + 1]
                    + ssq_sm[tid * 4 + 2] + ssq_sm[tid * 4 + 3];
            g_ssq_part[(size_t)m * 8 + bx] = s;
        }
    }
}

// ---------------------------------------------------------------------------
// normalize colbert rows: block = 2 rows (offset by row0). 2 threads compute
// scales (fixed-order 8-partial sum -> deterministic), then 128 threads/row
// rescale fp16 C into fp32 output.
// ---------------------------------------------------------------------------
__global__ void colbert_norm_kernel(float* __restrict__ Cout, int row0) {
    __shared__ float ssc[2];
    const int tid = threadIdx.x;
    const int base = row0 + blockIdx.x * 2;
    if (tid < 2) {
        const int rr = base + tid;
        float ss = 0.f;
        if (rr < MROWS) {
            const float* p = g_ssq_part + (size_t)rr * 8;
            #pragma unroll
            for (int n = 0; n < 8; n++) ss += p[n];
        }
        ssc[tid] = 1.f / fmaxf(sqrtf(ss), EPSV);
    }
    __syncthreads();
    const int row = base + (tid >> 7);
    if (row >= MROWS) return;
    const float sc = ssc[tid >> 7];
    const int col = (tid & 127) * 8;           // 8 halfs per thread
    const uint4 hv = *(const uint4*)(g_C + (size_t)row * HID + col);
    float2 f0 = __half22float2(*(const __half2*)&hv.x);
    float2 f1 = __half22float2(*(const __half2*)&hv.y);
    float2 f2 = __half22float2(*(const __half2*)&hv.z);
    float2 f3 = __half22float2(*(const __half2*)&hv.w);
    float* dst = Cout + (size_t)row * HID + col;
    *(float4*)dst       = make_float4(f0.x * sc, f0.y * sc, f1.x * sc, f1.y * sc);
    *(float4*)(dst + 4) = make_float4(f2.x * sc, f2.y * sc, f3.x * sc, f3.y * sc);
}

// ---------------------------------------------------------------------------
extern "C" void kernel_launch(void* const* d_in, const int* in_sizes, int n_in,
                              void* d_out, int out_size) {
    const float* hs  = (const float*)d_in[0];
    const float* am  = (const float*)d_in[1];
    const void*  ids = d_in[2];
    const float* sW  = (const float*)d_in[3];
    const float* sb  = (const float*)d_in[4];
    const float* cW  = (const float*)d_in[5];
    const float* cb  = (const float*)d_in[6];

    float* out     = (float*)d_out;
    float* dense   = out;
    float* sparse  = out + OFF_SPARSE;
    float* colbert = out + OFF_COLBERT;

    // one-time resources (created on the uncaptured correctness call)
    static cudaStream_t s_side = nullptr;
    static cudaEvent_t  e_fork = nullptr, e_join = nullptr, e_gA = nullptr,
                        e_n0 = nullptr;
    if (!s_side) {
        cudaStreamCreateWithFlags(&s_side, cudaStreamNonBlocking);
        cudaEventCreateWithFlags(&e_fork, cudaEventDisableTiming);
        cudaEventCreateWithFlags(&e_join, cudaEventDisableTiming);
        cudaEventCreateWithFlags(&e_gA,   cudaEventDisableTiming);
        cudaEventCreateWithFlags(&e_n0,   cudaEventDisableTiming);
        cudaFuncSetAttribute(colbert_mma_kernel,
                             cudaFuncAttributeMaxDynamicSharedMemorySize, SMEMB);
    }

    // fork: side stream runs the GEMM-independent small kernels
    cudaEventRecord(e_fork, 0);
    cudaStreamWaitEvent(s_side, e_fork, 0);
    wt_split_kernel<<<dim3(32, 32), 256, 0, s_side>>>(cW);
    dense_kernel<<<BATCH, 256, 0, s_side>>>(hs, dense);
    cudaEventRecord(e_join, s_side);

    // main chain: memset -> detect -> fused_prep
    cudaMemsetAsync(sparse, 0, (size_t)BATCH * VOCAB * sizeof(float), 0);
    detect_i64_kernel<<<1, 256>>>((const unsigned int*)ids);
    fused_prep_kernel<<<4096, 256>>>(hs, sW, sb, ids, sparse);

    // GEMM half A (rows < 16384), then half B; norm half0 overlaps half B.
    cudaStreamWaitEvent(0, e_join, 0);
    colbert_mma_kernel<<<dim3(8, YHALF), 256, SMEMB>>>(cb, am, 0);
    cudaEventRecord(e_gA, 0);
    colbert_mma_kernel<<<dim3(8, 256 - YHALF), 256, SMEMB>>>(cb, am, YHALF);

    cudaStreamWaitEvent(s_side, e_gA, 0);
    colbert_norm_kernel<<<NORMBLK_H0, 256, 0, s_side>>>(colbert, 0);
    cudaEventRecord(e_n0, s_side);

    colbert_norm_kernel<<<NORMBLK_H1, 256>>>(colbert, 16384);
    cudaStreamWaitEvent(0, e_n0, 0);
}